// round 7
// baseline (speedup 1.0000x reference)
#include <cuda_runtime.h>

// Residual_feature: residual = K3 * (K2 * (K1 * x)), each depthwise 5x5 conv
// with per-stage zero padding (pad=2). K1 has a 3x3 effective core, K3 is 1x3.
// Fused per-tile in shared memory with correct per-stage boundary zeroing.
//
// Tile: 32 rows (y) x 64 cols (x) of output per block, 128 threads.
// All stages computed in 4x4 register patches using float4 smem accesses.

#define IMG   512
#define TS_Y  32
#define TS_X  64
#define NTH   128

// smem region geometry (all strides multiple of 4 for float4 alignment):
//  input : rows [-3..34] x cols [-4..67]  -> 38 x 72  (valid cols 0..71)
//  edge  : rows [-2..33] x cols [-3..66]  -> 36 x 70 valid, stride 72 (pad)
//  tex   : rows [ 0..31] x cols [-1..64]  -> 32 x 66 valid, stride 68 (pad)

__global__ __launch_bounds__(NTH)
void residual_feature_kernel(const float* __restrict__ x,
                             float* __restrict__ out)
{
    __shared__ float sIN[38 * 72 + 8];   // +8 slack: stage-1 padded units may
    __shared__ float sED[36 * 72 + 8];   // read a few floats past the last row
    __shared__ float sTX[32 * 68 + 8];

    const int tid = threadIdx.x;
    const int bx = blockIdx.x;           // 0..7   (x tiles of 64)
    const int by = blockIdx.y;           // 0..15  (y tiles of 32)
    const long base = (long)blockIdx.z * (IMG * IMG);

    const int gy0in = by * TS_Y - 3;
    const int gx0in = bx * TS_X - 4;

    // ---------------- load input tile (38 rows x 18 float4) ----------------
    for (int t = tid; t < 38 * 18; t += NTH) {
        const int r = t / 18;
        const int k = t - r * 18;
        const int gy = gy0in + r;
        const int gx = gx0in + 4 * k;    // multiple of 4: fully in or fully out
        float4 v = make_float4(0.f, 0.f, 0.f, 0.f);
        if ((unsigned)gy < IMG && (unsigned)gx < IMG)
            v = *reinterpret_cast<const float4*>(&x[base + (long)gy * IMG + gx]);
        *reinterpret_cast<float4*>(&sIN[r * 72 + 4 * k]) = v;
    }
    __syncthreads();

    // ---------------- stage 1: edge = K1 * x (3x3 core) ----------------
    // edge[er][ec] uses sIN rows er..er+2, cols ec..ec+2.
    // 9 row-units x 18 col-units = 162 units (cols padded to 72; cols 70,71 garbage, never read)
    {
        const int gy0e = by * TS_Y - 2;
        const int gx0e = bx * TS_X - 3;
        for (int u = tid; u < 9 * 18; u += NTH) {
            const int ur = u / 18, uc = u - ur * 18;
            const int er0 = ur * 4, cb = uc * 4;
            float a[6][8];
            #pragma unroll
            for (int i = 0; i < 6; i++) {
                const float4 v0 = *reinterpret_cast<const float4*>(&sIN[(er0 + i) * 72 + cb]);
                const float4 v1 = *reinterpret_cast<const float4*>(&sIN[(er0 + i) * 72 + cb + 4]);
                a[i][0] = v0.x; a[i][1] = v0.y; a[i][2] = v0.z; a[i][3] = v0.w;
                a[i][4] = v1.x; a[i][5] = v1.y; a[i][6] = v1.z; a[i][7] = v1.w;
            }
            #pragma unroll
            for (int i = 0; i < 4; i++) {
                const int gye = gy0e + er0 + i;
                const bool rowok = ((unsigned)gye < IMG);
                float ev[4];
                #pragma unroll
                for (int j = 0; j < 4; j++) {
                    // [[-1,2,-1],[2,4,2],[-1,2,-1]]
                    const float c = a[i][j] + a[i][j+2] + a[i+2][j] + a[i+2][j+2];
                    const float e = a[i][j+1] + a[i+2][j+1] + a[i+1][j] + a[i+1][j+2];
                    float v = fmaf(4.f, a[i+1][j+1], fmaf(2.f, e, -c));
                    const int gxe = gx0e + cb + j;
                    ev[j] = (rowok && (unsigned)gxe < IMG) ? v : 0.f;   // zero-pad edge
                }
                *reinterpret_cast<float4*>(&sED[(er0 + i) * 72 + cb]) =
                    make_float4(ev[0], ev[1], ev[2], ev[3]);
            }
        }
    }
    __syncthreads();

    // ---------------- stage 2: texture = K2 * edge (5x5) ----------------
    // tex[tr][tc] uses sED rows tr..tr+4, cols tc..tc+4.
    // 8 row-units x 17 col-units = 136 units (cols padded to 68; 66,67 garbage)
    {
        const float W2[5][5] = {
            {-1.f,  2.f,  -2.f,  2.f, -1.f},
            { 2.f, -6.f,   8.f, -6.f,  2.f},
            {-2.f,  8.f, -12.f,  8.f, -2.f},
            { 2.f, -6.f,   8.f, -6.f,  2.f},
            {-1.f,  2.f,  -2.f,  2.f, -1.f}};
        const int gx0t = bx * TS_X - 1;  // tex rows are always inside the image
        for (int u = tid; u < 8 * 17; u += NTH) {
            const int ur = u / 17, uc = u - ur * 17;
            const int tr0 = ur * 4, cb = uc * 4;
            float acc[4][4];
            #pragma unroll
            for (int i = 0; i < 4; i++)
                #pragma unroll
                for (int j = 0; j < 4; j++) acc[i][j] = 0.f;

            #pragma unroll
            for (int k = 0; k < 8; k++) {          // stream 8 edge rows
                float b[8];
                const float4 v0 = *reinterpret_cast<const float4*>(&sED[(tr0 + k) * 72 + cb]);
                const float4 v1 = *reinterpret_cast<const float4*>(&sED[(tr0 + k) * 72 + cb + 4]);
                b[0] = v0.x; b[1] = v0.y; b[2] = v0.z; b[3] = v0.w;
                b[4] = v1.x; b[5] = v1.y; b[6] = v1.z; b[7] = v1.w;
                #pragma unroll
                for (int i = 0; i < 4; i++) {
                    const int w = k - i;           // weight row (dy+2)
                    if (w >= 0 && w <= 4) {
                        #pragma unroll
                        for (int j = 0; j < 4; j++) {
                            float s = acc[i][j];
                            s = fmaf(W2[w][0], b[j    ], s);
                            s = fmaf(W2[w][1], b[j + 1], s);
                            s = fmaf(W2[w][2], b[j + 2], s);
                            s = fmaf(W2[w][3], b[j + 3], s);
                            s = fmaf(W2[w][4], b[j + 4], s);
                            acc[i][j] = s;
                        }
                    }
                }
            }
            #pragma unroll
            for (int i = 0; i < 4; i++) {
                float tv[4];
                #pragma unroll
                for (int j = 0; j < 4; j++) {
                    const int gxt = gx0t + cb + j;
                    tv[j] = ((unsigned)gxt < IMG) ? acc[i][j] : 0.f;   // zero-pad texture
                }
                *reinterpret_cast<float4*>(&sTX[(tr0 + i) * 68 + cb]) =
                    make_float4(tv[0], tv[1], tv[2], tv[3]);
            }
        }
    }
    __syncthreads();

    // ---------------- stage 3: residual = K3 * texture (1x3) ----------------
    // out[oy][ox] = tex[oy][ox] - 2*tex[oy][ox+1] + tex[oy][ox+2]  (tc = ox+1+dx)
    {
        const int u = tid;                 // exactly 128 units: 8 row x 16 col
        const int ur = u >> 4, uc = u & 15;
        const int oy0 = ur * 4, cb = uc * 4;
        const int gx = bx * TS_X + cb;
        #pragma unroll
        for (int i = 0; i < 4; i++) {
            const float4 v0 = *reinterpret_cast<const float4*>(&sTX[(oy0 + i) * 68 + cb]);
            const float4 v1 = *reinterpret_cast<const float4*>(&sTX[(oy0 + i) * 68 + cb + 4]);
            const float t0 = v0.x, t1 = v0.y, t2 = v0.z, t3 = v0.w, t4 = v1.x, t5 = v1.y;
            float4 r;
            r.x = fmaf(-2.f, t1, t0 + t2);
            r.y = fmaf(-2.f, t2, t1 + t3);
            r.z = fmaf(-2.f, t3, t2 + t4);
            r.w = fmaf(-2.f, t4, t3 + t5);
            const int gy = by * TS_Y + oy0 + i;
            *reinterpret_cast<float4*>(&out[base + (long)gy * IMG + gx]) = r;
        }
    }
}

extern "C" void kernel_launch(void* const* d_in, const int* in_sizes, int n_in,
                              void* d_out, int out_size)
{
    const float* x = (const float*)d_in[0];
    float* out = (float*)d_out;
    const int planes = in_sizes[0] / (IMG * IMG);   // 64*3 = 192

    dim3 grid(IMG / TS_X, IMG / TS_Y, planes);      // (8, 16, 192)
    dim3 block(NTH);
    residual_feature_kernel<<<grid, block>>>(x, out);
}